// round 7
// baseline (speedup 1.0000x reference)
#include <cuda_runtime.h>
#include <math.h>

#define NUM_ITEMS  10000
#define NUM_USERS  10000
#define NUM_GROUPS 5000
#define EMB_DIM    64
#define BATCH      16384

#define WCAP        1024      // per-warp hit-index buffer (4 KB)
#define NBLOCKS     1250      // 1250 blocks x 8 warps = 10000 warps
#define NWARPS_TOT  10000     // k1: exactly 1 row/warp; k2: half the warps idle

// Scratch (allocation-free rule: __device__ globals)
__device__ float g_user_embeds[NUM_USERS * EMB_DIM];   // 2.56 MB
__device__ float g_group_embeds[NUM_GROUPS * EMB_DIM]; // 1.28 MB

// ---------------------------------------------------------------------------
// Batched gather, software-pipelined: batch j+1's loads are issued before
// batch j's accumulates, so only ONE L2 latency is exposed per flush.
// ---------------------------------------------------------------------------
__device__ __forceinline__ void load_batch(const int* __restrict__ idxbuf, int j,
                                           int lane, const float2* __restrict__ emb2,
                                           float2* e)
{
    int id[8];
    #pragma unroll
    for (int t = 0; t < 8; ++t) id[t] = idxbuf[j + t];           // LDS broadcast
    #pragma unroll
    for (int t = 0; t < 8; ++t) e[t] = emb2[id[t] * 32 + lane];  // 8 indep LDG.64
}

__device__ __forceinline__ void gather_accumulate(const int* __restrict__ idxbuf,
                                                  int nh, int lane,
                                                  const float2* __restrict__ emb2,
                                                  float2& acc)
{
    const int nfull = nh & ~7;
    if (nfull) {
        float2 ea[8];
        load_batch(idxbuf, 0, lane, emb2, ea);
        for (int j = 8; j < nfull; j += 8) {
            float2 eb[8];
            load_batch(idxbuf, j, lane, emb2, eb);       // in flight while...
            #pragma unroll
            for (int t = 0; t < 8; ++t) { acc.x += ea[t].x; acc.y += ea[t].y; }
            #pragma unroll
            for (int t = 0; t < 8; ++t) ea[t] = eb[t];
        }
        #pragma unroll
        for (int t = 0; t < 8; ++t) { acc.x += ea[t].x; acc.y += ea[t].y; }
    }
    for (int j = nfull; j < nh; ++j) {
        const float2 e = emb2[idxbuf[j] * 32 + lane];
        acc.x += e.x; acc.y += e.y;
    }
}

// ---------------------------------------------------------------------------
// One warp per row (grid-strided).
// Per 4KB block: 8x LDG.128 prefetch; byte-pack detection (PRMT) -> 1 bit/elem;
// dp4a count; warp shfl-scan; lane-parallel index writes to smem.
// Gather deferred until buffer full or row end (typically once per row).
// Matrix entries are exactly {0.0f, 1.0f}: byte3 == 0x3F iff hit, and the
// divisor count equals the number of hits.
// ---------------------------------------------------------------------------
template <int NCOLS, bool CLAMP>
__global__ __launch_bounds__(256, 4)
void row_aggregate_kernel(const float* __restrict__ mat,
                          const float* __restrict__ emb,
                          float* __restrict__ out,
                          int nrows)
{
    __shared__ int s_idx[8][WCAP];                // 32 KB / block

    const int lane = threadIdx.x & 31;
    const int wl   = threadIdx.x >> 5;
    const int gw   = blockIdx.x * 8 + wl;
    int* idxbuf = s_idx[wl];
    const float2* __restrict__ emb2 = (const float2*)emb;
    const int ncols4 = NCOLS / 4;                 // 2500

    for (int row = gw; row < nrows; row += NWARPS_TOT) {
        const float4* __restrict__ row4 = (const float4*)(mat + (size_t)row * NCOLS);
        float2 acc = make_float2(0.f, 0.f);
        int nh = 0, tot = 0;

        for (int base = 0; base < ncols4; base += 256) {
            // ---- prefetch 8 independent float4 loads (MLP=8 stream) ----
            float4 v[8];
            #pragma unroll
            for (int u = 0; u < 8; ++u) {
                const int jj = base + u * 32 + lane;
                v[u] = (jj < ncols4) ? row4[jj] : make_float4(0.f, 0.f, 0.f, 0.f);
            }

            // ---- byte-pack detection: br[u] bit 8c set iff element c hit ----
            unsigned br[8];
            unsigned ucnt = 0u;
            #pragma unroll
            for (int u = 0; u < 8; ++u) {
                const unsigned x = __float_as_uint(v[u].x);
                const unsigned y = __float_as_uint(v[u].y);
                const unsigned z = __float_as_uint(v[u].z);
                const unsigned w = __float_as_uint(v[u].w);
                // [b3(x), b3(y), 0, 0] | [0, 0, b3(z), b3(w)]  (b3 of 1.0f = 0x3F)
                const unsigned p = __byte_perm(x, y, 0x0073) |
                                   __byte_perm(z, w, 0x7300);
                br[u] = p & 0x01010101u;
                ucnt = __dp4a(br[u], 0x01010101u, ucnt);
            }
            const int cnt = (int)ucnt;

            // ---- warp inclusive scan of per-lane counts ----
            int xs = cnt;
            #pragma unroll
            for (int d = 1; d < 32; d <<= 1) {
                const int y2 = __shfl_up_sync(0xffffffffu, xs, d);
                if (lane >= d) xs += y2;
            }
            const int btot = __shfl_sync(0xffffffffu, xs, 31);

            // ---- flush if the block's hits wouldn't fit ----
            if (nh + btot > WCAP) {
                __syncwarp();
                gather_accumulate(idxbuf, nh, lane, emb2, acc);
                tot += nh; nh = 0;
                __syncwarp();
            }

            // ---- lane-parallel index writes at scanned offsets ----
            int off = nh + xs - cnt;                    // exclusive prefix
            const int ebase = base * 4 + lane * 4;
            #pragma unroll
            for (int u = 0; u < 8; ++u) {
                unsigned b = br[u];
                while (b) {
                    const int k = __ffs(b) - 1;         // bit 8c
                    b &= b - 1;
                    idxbuf[off++] = ebase + u * 128 + (k >> 3);
                }
            }
            nh += btot;
            __syncwarp();
        }

        // ---- row-end gather (typically the only one) ----
        gather_accumulate(idxbuf, nh, lane, emb2, acc);
        tot += nh;
        __syncwarp();                                   // buffer reuse next row

        float div = (float)tot;
        if (CLAMP) div = fmaxf(div, 1.0f);
        const float inv = 1.0f / div;

        float2* __restrict__ out2 = (float2*)(out + (size_t)row * EMB_DIM);
        out2[lane] = make_float2(acc.x * inv, acc.y * inv);
    }
}

// ---------------------------------------------------------------------------
// MLP: y = sigmoid(relu([ge[g], ie[it]] @ W1 + b1) @ W2 + b2)
// ---------------------------------------------------------------------------
__global__ void mlp_kernel(const float* __restrict__ group_embeds,
                           const float* __restrict__ item_emb,
                           const float* __restrict__ W1,  // [128, 8]
                           const float* __restrict__ b1,  // [8]
                           const float* __restrict__ W2,  // [8, 1]
                           const float* __restrict__ b2,  // [1]
                           const int*   __restrict__ gidx,
                           const int*   __restrict__ iidx,
                           float* __restrict__ out,
                           int batch)
{
    __shared__ float sW1[2 * EMB_DIM * 8];
    __shared__ float sb1[8];
    __shared__ float sW2[8];
    __shared__ float sb2;

    for (int i = threadIdx.x; i < 2 * EMB_DIM * 8; i += blockDim.x)
        sW1[i] = W1[i];
    if (threadIdx.x < 8) {
        sb1[threadIdx.x] = b1[threadIdx.x];
        sW2[threadIdx.x] = W2[threadIdx.x];
    }
    if (threadIdx.x == 0) sb2 = b2[0];
    __syncthreads();

    const int i = blockIdx.x * blockDim.x + threadIdx.x;
    if (i >= batch) return;

    const int g  = gidx[i];
    const int it = iidx[i];
    const float2* __restrict__ ge2 =
        (const float2*)(group_embeds + (size_t)g * EMB_DIM);
    const float2* __restrict__ ie2 =
        (const float2*)(item_emb + (size_t)it * EMB_DIM);

    float h[8];
    #pragma unroll
    for (int k = 0; k < 8; ++k) h[k] = sb1[k];

    #pragma unroll 4
    for (int d2 = 0; d2 < 32; ++d2) {
        const float2 e = ge2[d2];
        const int d0 = 2 * d2;
        #pragma unroll
        for (int k = 0; k < 8; ++k) {
            h[k] += e.x * sW1[(d0    ) * 8 + k];
            h[k] += e.y * sW1[(d0 + 1) * 8 + k];
        }
    }
    #pragma unroll 4
    for (int d2 = 0; d2 < 32; ++d2) {
        const float2 e = ie2[d2];
        const int d0 = 2 * d2 + EMB_DIM;
        #pragma unroll
        for (int k = 0; k < 8; ++k) {
            h[k] += e.x * sW1[(d0    ) * 8 + k];
            h[k] += e.y * sW1[(d0 + 1) * 8 + k];
        }
    }

    float y = sb2;
    #pragma unroll
    for (int k = 0; k < 8; ++k)
        y += fmaxf(h[k], 0.0f) * sW2[k];

    out[i] = 1.0f / (1.0f + expf(-y));
}

// ---------------------------------------------------------------------------
extern "C" void kernel_launch(void* const* d_in, const int* in_sizes, int n_in,
                              void* d_out, int out_size)
{
    const float* item_emb = (const float*)d_in[0];
    const float* ui       = (const float*)d_in[1];
    const float* gu       = (const float*)d_in[2];
    const float* W1       = (const float*)d_in[3];
    const float* b1       = (const float*)d_in[4];
    const float* W2       = (const float*)d_in[5];
    const float* b2       = (const float*)d_in[6];
    const int*   gidx     = (const int*)d_in[7];
    const int*   iidx     = (const int*)d_in[8];
    float* out            = (float*)d_out;

    float* user_embeds;
    float* group_embeds;
    cudaGetSymbolAddress((void**)&user_embeds,  g_user_embeds);
    cudaGetSymbolAddress((void**)&group_embeds, g_group_embeds);

    // Kernel 1: user_embeds = (ui @ item_emb) / clamp(count, 1)
    row_aggregate_kernel<NUM_ITEMS, true>
        <<<NBLOCKS, 256>>>(ui, item_emb, user_embeds, NUM_USERS);

    // Kernel 2: group_embeds = (gu @ user_embeds) / count   (raw, no clamp)
    row_aggregate_kernel<NUM_USERS, false>
        <<<NBLOCKS, 256>>>(gu, user_embeds, group_embeds, NUM_GROUPS);

    // Kernel 3: MLP head
    {
        const int threads = 128;
        const int grid = (BATCH + threads - 1) / threads;
        mlp_kernel<<<grid, threads>>>(group_embeds, item_emb,
                                      W1, b1, W2, b2, gidx, iidx,
                                      out, BATCH);
    }
}

// round 8
// speedup vs baseline: 1.0201x; 1.0201x over previous
#include <cuda_runtime.h>
#include <math.h>

#define NUM_ITEMS  10000
#define NUM_USERS  10000
#define NUM_GROUPS 5000
#define EMB_DIM    64
#define BATCH      16384

#define WCAP     1024         // per-warp hit-index buffer (4 KB)
#define NBLOCKS  1250         // x 8 warps = 10000 warps = one task each

// Scratch (allocation-free rule: __device__ globals)
__device__ float g_user_embeds[NUM_USERS * EMB_DIM];   // 2.56 MB
__device__ float g_group_embeds[NUM_GROUPS * EMB_DIM]; // 1.28 MB

// ---------------------------------------------------------------------------
// Batched gather, software-pipelined: batch j+1's loads are issued before
// batch j's accumulates, so only ONE L2 latency is exposed per flush.
// ---------------------------------------------------------------------------
__device__ __forceinline__ void load_batch(const int* __restrict__ idxbuf, int j,
                                           int lane, const float2* __restrict__ emb2,
                                           float2* e)
{
    int id[8];
    #pragma unroll
    for (int t = 0; t < 8; ++t) id[t] = idxbuf[j + t];           // LDS broadcast
    #pragma unroll
    for (int t = 0; t < 8; ++t) e[t] = emb2[id[t] * 32 + lane];  // 8 indep LDG.64
}

__device__ __forceinline__ void gather_accumulate(const int* __restrict__ idxbuf,
                                                  int nh, int lane,
                                                  const float2* __restrict__ emb2,
                                                  float2& acc)
{
    const int nfull = nh & ~7;
    if (nfull) {
        float2 ea[8];
        load_batch(idxbuf, 0, lane, emb2, ea);
        for (int j = 8; j < nfull; j += 8) {
            float2 eb[8];
            load_batch(idxbuf, j, lane, emb2, eb);       // in flight while...
            #pragma unroll
            for (int t = 0; t < 8; ++t) { acc.x += ea[t].x; acc.y += ea[t].y; }
            #pragma unroll
            for (int t = 0; t < 8; ++t) ea[t] = eb[t];
        }
        #pragma unroll
        for (int t = 0; t < 8; ++t) { acc.x += ea[t].x; acc.y += ea[t].y; }
    }
    for (int j = nfull; j < nh; ++j) {
        const float2 e = emb2[idxbuf[j] * 32 + lane];
        acc.x += e.x; acc.y += e.y;
    }
}

// ---------------------------------------------------------------------------
// SPLIT=false: one warp scans one full row (k1, 10000 rows = 10000 warps).
// SPLIT=true : warp pair (2i, 2i+1) scans the two column-halves of row i
//              (k2, 5000 rows = 10000 warps); partials combined via smem.
// Per 4KB block: 8x LDG.128 prefetch; byte-pack detection (PRMT) -> 1 bit/elem;
// REDUX total + smem atomicAdd slot allocation (index order is irrelevant);
// lane-parallel index writes. Gather deferred to row end (typically once).
// Matrix entries are exactly {0.0f, 1.0f}: byte3 == 0x3F iff hit.
// ---------------------------------------------------------------------------
template <int NCOLS, bool CLAMP, bool SPLIT>
__global__ __launch_bounds__(256, 4)
void row_aggregate_kernel(const float* __restrict__ mat,
                          const float* __restrict__ emb,
                          float* __restrict__ out,
                          int nrows)
{
    __shared__ int    s_idx[8][WCAP];             // 32 KB
    __shared__ int    s_nh[8];
    __shared__ float2 s_part[8][32];              // pair-combine (SPLIT)
    __shared__ int    s_tot[8];

    const int lane = threadIdx.x & 31;
    const int wl   = threadIdx.x >> 5;
    const int gw   = blockIdx.x * 8 + wl;

    const int ncols4 = NCOLS / 4;
    int row, c4b, c4e;
    bool active;
    if (SPLIT) {
        row = gw >> 1;
        const int half = gw & 1;
        c4b = half * (ncols4 / 2);
        c4e = c4b + (ncols4 - ncols4 / 2) * half + (ncols4 / 2) * (1 - half);
        // i.e. half0: [0, n/2), half1: [n/2, n)
        c4e = half ? ncols4 : (ncols4 / 2);
        active = (row < nrows);
    } else {
        row = gw; c4b = 0; c4e = ncols4;
        active = (row < nrows);
    }

    int* idxbuf = s_idx[wl];
    const float2* __restrict__ emb2 = (const float2*)emb;

    float2 acc = make_float2(0.f, 0.f);
    int tot = 0;

    if (active) {
        const float4* __restrict__ row4 = (const float4*)(mat + (size_t)row * NCOLS);
        if (lane == 0) s_nh[wl] = 0;
        __syncwarp();
        int nh = 0;

        for (int base = c4b; base < c4e; base += 256) {
            // ---- prefetch 8 independent float4 loads (MLP=8 stream) ----
            float4 v[8];
            #pragma unroll
            for (int u = 0; u < 8; ++u) {
                const int jj = base + u * 32 + lane;
                v[u] = (jj < c4e) ? row4[jj] : make_float4(0.f, 0.f, 0.f, 0.f);
            }

            // ---- byte-pack detection: br[u] bit 8c set iff element c hit ----
            unsigned br[8];
            unsigned ucnt = 0u;
            #pragma unroll
            for (int u = 0; u < 8; ++u) {
                const unsigned x = __float_as_uint(v[u].x);
                const unsigned y = __float_as_uint(v[u].y);
                const unsigned z = __float_as_uint(v[u].z);
                const unsigned w = __float_as_uint(v[u].w);
                const unsigned p = __byte_perm(x, y, 0x0073) |
                                   __byte_perm(z, w, 0x7300);
                br[u] = p & 0x01010101u;
                ucnt = __dp4a(br[u], 0x01010101u, ucnt);
            }
            const int cnt = (int)ucnt;

            // ---- block total (1 instr) + flush check ----
            const int btot = __reduce_add_sync(0xffffffffu, cnt);
            if (nh + btot > WCAP) {
                __syncwarp();
                gather_accumulate(idxbuf, nh, lane, emb2, acc);
                tot += nh; nh = 0;
                if (lane == 0) s_nh[wl] = 0;
                __syncwarp();
            }

            // ---- slot allocation via smem atomic (order-free) ----
            int off = atomicAdd(&s_nh[wl], cnt);
            const int ebase = base * 4 + lane * 4;
            #pragma unroll
            for (int u = 0; u < 8; ++u) {
                unsigned b = br[u];
                while (b) {
                    const int k = __ffs(b) - 1;          // bit 8c
                    b &= b - 1;
                    idxbuf[off++] = ebase + u * 128 + (k >> 3);
                }
            }
            nh += btot;
            __syncwarp();
        }

        // ---- row-end gather (typically the only one) ----
        gather_accumulate(idxbuf, nh, lane, emb2, acc);
        tot += nh;
    }

    if (SPLIT) {
        // combine warp pair (2i even half, 2i+1 odd half); finalize in odd warp
        if (active && (wl & 1) == 0) {
            s_part[wl][lane] = acc;
            if (lane == 0) s_tot[wl] = tot;
        }
        __syncthreads();
        if (active && (wl & 1) == 1) {
            const float2 o = s_part[wl - 1][lane];
            acc.x += o.x; acc.y += o.y;
            tot += s_tot[wl - 1];

            float div = (float)tot;
            if (CLAMP) div = fmaxf(div, 1.0f);
            const float inv = 1.0f / div;
            float2* __restrict__ out2 = (float2*)(out + (size_t)row * EMB_DIM);
            out2[lane] = make_float2(acc.x * inv, acc.y * inv);
        }
    } else if (active) {
        float div = (float)tot;
        if (CLAMP) div = fmaxf(div, 1.0f);
        const float inv = 1.0f / div;
        float2* __restrict__ out2 = (float2*)(out + (size_t)row * EMB_DIM);
        out2[lane] = make_float2(acc.x * inv, acc.y * inv);
    }
}

// ---------------------------------------------------------------------------
// MLP: y = sigmoid(relu([ge[g], ie[it]] @ W1 + b1) @ W2 + b2)
// ---------------------------------------------------------------------------
__global__ void mlp_kernel(const float* __restrict__ group_embeds,
                           const float* __restrict__ item_emb,
                           const float* __restrict__ W1,  // [128, 8]
                           const float* __restrict__ b1,  // [8]
                           const float* __restrict__ W2,  // [8, 1]
                           const float* __restrict__ b2,  // [1]
                           const int*   __restrict__ gidx,
                           const int*   __restrict__ iidx,
                           float* __restrict__ out,
                           int batch)
{
    __shared__ float sW1[2 * EMB_DIM * 8];
    __shared__ float sb1[8];
    __shared__ float sW2[8];
    __shared__ float sb2;

    for (int i = threadIdx.x; i < 2 * EMB_DIM * 8; i += blockDim.x)
        sW1[i] = W1[i];
    if (threadIdx.x < 8) {
        sb1[threadIdx.x] = b1[threadIdx.x];
        sW2[threadIdx.x] = W2[threadIdx.x];
    }
    if (threadIdx.x == 0) sb2 = b2[0];
    __syncthreads();

    const int i = blockIdx.x * blockDim.x + threadIdx.x;
    if (i >= batch) return;

    const int g  = gidx[i];
    const int it = iidx[i];
    const float2* __restrict__ ge2 =
        (const float2*)(group_embeds + (size_t)g * EMB_DIM);
    const float2* __restrict__ ie2 =
        (const float2*)(item_emb + (size_t)it * EMB_DIM);

    float h[8];
    #pragma unroll
    for (int k = 0; k < 8; ++k) h[k] = sb1[k];

    #pragma unroll 4
    for (int d2 = 0; d2 < 32; ++d2) {
        const float2 e = ge2[d2];
        const int d0 = 2 * d2;
        #pragma unroll
        for (int k = 0; k < 8; ++k) {
            h[k] += e.x * sW1[(d0    ) * 8 + k];
            h[k] += e.y * sW1[(d0 + 1) * 8 + k];
        }
    }
    #pragma unroll 4
    for (int d2 = 0; d2 < 32; ++d2) {
        const float2 e = ie2[d2];
        const int d0 = 2 * d2 + EMB_DIM;
        #pragma unroll
        for (int k = 0; k < 8; ++k) {
            h[k] += e.x * sW1[(d0    ) * 8 + k];
            h[k] += e.y * sW1[(d0 + 1) * 8 + k];
        }
    }

    float y = sb2;
    #pragma unroll
    for (int k = 0; k < 8; ++k)
        y += fmaxf(h[k], 0.0f) * sW2[k];

    out[i] = 1.0f / (1.0f + expf(-y));
}

// ---------------------------------------------------------------------------
extern "C" void kernel_launch(void* const* d_in, const int* in_sizes, int n_in,
                              void* d_out, int out_size)
{
    const float* item_emb = (const float*)d_in[0];
    const float* ui       = (const float*)d_in[1];
    const float* gu       = (const float*)d_in[2];
    const float* W1       = (const float*)d_in[3];
    const float* b1       = (const float*)d_in[4];
    const float* W2       = (const float*)d_in[5];
    const float* b2       = (const float*)d_in[6];
    const int*   gidx     = (const int*)d_in[7];
    const int*   iidx     = (const int*)d_in[8];
    float* out            = (float*)d_out;

    float* user_embeds;
    float* group_embeds;
    cudaGetSymbolAddress((void**)&user_embeds,  g_user_embeds);
    cudaGetSymbolAddress((void**)&group_embeds, g_group_embeds);

    // Kernel 1: user_embeds = (ui @ item_emb) / clamp(count, 1)
    // 10000 warps, one full row each.
    row_aggregate_kernel<NUM_ITEMS, true, false>
        <<<NBLOCKS, 256>>>(ui, item_emb, user_embeds, NUM_USERS);

    // Kernel 2: group_embeds = (gu @ user_embeds) / count  (raw, no clamp)
    // 10000 warps, one half-row each (warp pairs combine).
    row_aggregate_kernel<NUM_USERS, false, true>
        <<<NBLOCKS, 256>>>(gu, user_embeds, group_embeds, NUM_GROUPS);

    // Kernel 3: MLP head
    {
        const int threads = 128;
        const int grid = (BATCH + threads - 1) / threads;
        mlp_kernel<<<grid, threads>>>(group_embeds, item_emb,
                                      W1, b1, W2, b2, gidx, iidx,
                                      out, BATCH);
    }
}